// round 14
// baseline (speedup 1.0000x reference)
#include <cuda_runtime.h>
#include <cuda_bf16.h>
#include <cstdint>

#define D_MODEL 2048
#define NHEAD   16
#define HD      128
#define TSEQ    1024
#define BATCH   4
#define MTOT    (BATCH * TSEQ)     // 4096
#define NQKV    (3 * D_MODEL)      // 6144

// ---------------------------------------------------------------------------
// Scratch (__device__ globals — allocation-guard safe), 16B-aligned
// ---------------------------------------------------------------------------
__device__ __align__(16) __nv_bfloat16 g_qkvhi[MTOT * NQKV];
__device__ __align__(16) __nv_bfloat16 g_qkvlo[MTOT * NQKV];
__device__ __align__(16) __nv_bfloat16 g_xhi[MTOT * D_MODEL];
__device__ __align__(16) __nv_bfloat16 g_xlo[MTOT * D_MODEL];
__device__ __align__(16) __nv_bfloat16 g_ahi[MTOT * D_MODEL];
__device__ __align__(16) __nv_bfloat16 g_alo[MTOT * D_MODEL];
__device__ __align__(16) __nv_bfloat16 g_wqhi[NQKV * D_MODEL];
__device__ __align__(16) __nv_bfloat16 g_wqlo[NQKV * D_MODEL];
__device__ __align__(16) __nv_bfloat16 g_wphi[D_MODEL * D_MODEL];
__device__ __align__(16) __nv_bfloat16 g_wplo[D_MODEL * D_MODEL];

// ---------------------------------------------------------------------------
// helpers
// ---------------------------------------------------------------------------
__device__ __forceinline__ uint32_t smem_u32(const void* p) {
    uint32_t a;
    asm("{ .reg .u64 t; cvta.to.shared.u64 t, %1; cvt.u32.u64 %0, t; }"
        : "=r"(a) : "l"(p));
    return a;
}
__device__ __forceinline__ void cpa16(uint32_t dst, const void* src) {
    asm volatile("cp.async.cg.shared.global [%0], [%1], 16;" :: "r"(dst), "l"(src));
}
__device__ __forceinline__ void cp_commit() { asm volatile("cp.async.commit_group;"); }
template <int N> __device__ __forceinline__ void cp_wait() {
    asm volatile("cp.async.wait_group %0;" :: "n"(N));
}
__device__ __forceinline__ void ldsm4(uint32_t* r, uint32_t a) {
    asm volatile("ldmatrix.sync.aligned.m8n8.x4.shared.b16 {%0,%1,%2,%3}, [%4];"
        : "=r"(r[0]), "=r"(r[1]), "=r"(r[2]), "=r"(r[3]) : "r"(a));
}
__device__ __forceinline__ void ldsm4t(uint32_t* r, uint32_t a) {
    asm volatile("ldmatrix.sync.aligned.m8n8.x4.trans.shared.b16 {%0,%1,%2,%3}, [%4];"
        : "=r"(r[0]), "=r"(r[1]), "=r"(r[2]), "=r"(r[3]) : "r"(a));
}
__device__ __forceinline__ void mma_bf16(float* c, const uint32_t* a,
                                         const uint32_t* b) {
    asm volatile(
        "mma.sync.aligned.m16n8k16.row.col.f32.bf16.bf16.f32 "
        "{%0,%1,%2,%3}, {%4,%5,%6,%7}, {%8,%9}, {%0,%1,%2,%3};"
        : "+f"(c[0]), "+f"(c[1]), "+f"(c[2]), "+f"(c[3])
        : "r"(a[0]), "r"(a[1]), "r"(a[2]), "r"(a[3]), "r"(b[0]), "r"(b[1]));
}
__device__ __forceinline__ uint32_t packbf(float e0, float e1) {
    uint32_t r;
    asm("cvt.rn.bf16x2.f32 %0, %1, %2;" : "=r"(r) : "f"(e1), "f"(e0));
    return r;
}
__device__ __forceinline__ uint32_t lopackbf(uint32_t hipack, float e0, float e1) {
    float h0 = __uint_as_float(hipack << 16);
    float h1 = __uint_as_float(hipack & 0xffff0000u);
    return packbf(e0 - h0, e1 - h1);
}
__device__ __forceinline__ float ex2f(float x) {
    float y;
    asm("ex2.approx.ftz.f32 %0, %1;" : "=f"(y) : "f"(x));
    return y;
}
// 64B-row swizzle: bits [4:5] ^= bits [7:8]; apply to full sub-bit-10 offset.
__device__ __forceinline__ uint32_t swz(uint32_t off) {
    return off ^ (((off >> 7) & 3u) << 4);
}

// ---------------------------------------------------------------------------
// Split fp32 -> (hi, lo) bf16 (elementwise)
// ---------------------------------------------------------------------------
__global__ __launch_bounds__(256)
void split_kernel(const float* __restrict__ in, __nv_bfloat16* __restrict__ hi,
                  __nv_bfloat16* __restrict__ lo, int n)
{
    int i = (blockIdx.x * 256 + threadIdx.x) * 4;
    if (i >= n) return;
    float4 v = *(const float4*)(in + i);
    uint32_t h0 = packbf(v.x, v.y);
    uint32_t h1 = packbf(v.z, v.w);
    *(uint32_t*)(hi + i)     = h0;
    *(uint32_t*)(hi + i + 2) = h1;
    *(uint32_t*)(lo + i)     = lopackbf(h0, v.x, v.y);
    *(uint32_t*)(lo + i + 2) = lopackbf(h1, v.z, v.w);
}

// ---------------------------------------------------------------------------
// Transpose + split: W fp32 [K][N] -> Whi/Wlo bf16 [N][K]
// ---------------------------------------------------------------------------
__global__ __launch_bounds__(256)
void tsplit_kernel(const float* __restrict__ W, __nv_bfloat16* __restrict__ hi,
                   __nv_bfloat16* __restrict__ lo, int K, int N)
{
    __shared__ float t[32][33];
    const int n0 = blockIdx.x * 32, k0 = blockIdx.y * 32;
    const int x = threadIdx.x & 31, y = threadIdx.x >> 5;
#pragma unroll
    for (int i = 0; i < 4; i++)
        t[y + 8 * i][x] = W[(size_t)(k0 + y + 8 * i) * N + n0 + x];
    __syncthreads();
#pragma unroll
    for (int i = 0; i < 4; i++) {
        float v = t[x][y + 8 * i];
        __nv_bfloat16 h = __float2bfloat16(v);
        size_t o = (size_t)(n0 + y + 8 * i) * K + k0 + x;
        hi[o] = h;
        lo[o] = __float2bfloat16(v - __bfloat162float(h));
    }
}

// ---------------------------------------------------------------------------
// HMMA bf16x3 GEMM — byte-identical to round 9/11/13 (proven 72% tensor)
// ---------------------------------------------------------------------------
#define BKC        32
#define OPB        (128 * 64)
#define STGB       (4 * OPB)
#define NSTG       3
#define GEMM_SMEM  (NSTG * STGB)

__device__ __forceinline__ void load_op(uint32_t dstb,
                                        const __nv_bfloat16* __restrict__ src,
                                        int r0, int k0, int K, int tid)
{
#pragma unroll
    for (int t = 0; t < 2; t++) {
        const int i = tid + t * 256;
        const int row = i >> 2, seg = i & 3;
        cpa16(dstb + swz((uint32_t)(row * 64 + seg * 16)),
              src + (size_t)(r0 + row) * K + k0 + seg * 8);
    }
}

__device__ __forceinline__ void load_stage(
    uint32_t sbase,
    const __nv_bfloat16* __restrict__ Ahi, const __nv_bfloat16* __restrict__ Alo,
    const __nv_bfloat16* __restrict__ Bhi, const __nv_bfloat16* __restrict__ Blo,
    int m0, int n0, int k0, int K, int tid)
{
    load_op(sbase + 0 * OPB, Ahi, m0, k0, K, tid);
    load_op(sbase + 1 * OPB, Alo, m0, k0, K, tid);
    load_op(sbase + 2 * OPB, Bhi, n0, k0, K, tid);
    load_op(sbase + 3 * OPB, Blo, n0, k0, K, tid);
}

__global__ __launch_bounds__(256, 2)
void gemm_hmma(const __nv_bfloat16* __restrict__ Ahi,
               const __nv_bfloat16* __restrict__ Alo,
               const __nv_bfloat16* __restrict__ Bhi,
               const __nv_bfloat16* __restrict__ Blo,
               float* __restrict__ Cf,
               __nv_bfloat16* __restrict__ Chi,
               __nv_bfloat16* __restrict__ Clo,
               int M, int N, int K)
{
    extern __shared__ char smc[];
    const uint32_t sb = smem_u32(smc);
    const int tid  = threadIdx.x;
    const int wid  = tid >> 5, lane = tid & 31;
    const int wm   = wid >> 2;
    const int wn   = wid & 3;
    const int g    = lane >> 2;
    const int tig  = lane & 3;
    const int m0 = blockIdx.y * 128, n0 = blockIdx.x * 128;

    const int lrow  = lane & 15;
    const int lhalf = lane >> 4;
    const int brow  = (lane & 7) | ((lane & 16) >> 1);
    const int bhalf = (lane >> 3) & 1;

    uint32_t aoff[2], boff[2];
#pragma unroll
    for (int ks = 0; ks < 2; ks++) {
        aoff[ks] = swz((uint32_t)((wm * 64 + lrow) * 64 + lhalf * 16 + ks * 32));
        boff[ks] = swz((uint32_t)((wn * 32 + brow) * 64 + bhalf * 16 + ks * 32));
    }

    float acc[4][4][4];
#pragma unroll
    for (int mt = 0; mt < 4; mt++)
#pragma unroll
        for (int nt = 0; nt < 4; nt++)
#pragma unroll
            for (int q = 0; q < 4; q++) acc[mt][nt][q] = 0.0f;

    const int NC = K / BKC;

    load_stage(sb, Ahi, Alo, Bhi, Blo, m0, n0, 0, K, tid);
    cp_commit();
    load_stage(sb + STGB, Ahi, Alo, Bhi, Blo, m0, n0, BKC, K, tid);
    cp_commit();

    int st_idx = 0;
    for (int kc = 0; kc < NC; kc++) {
        if (kc + 1 < NC) cp_wait<1>(); else cp_wait<0>();
        __syncthreads();

        if (kc + 2 < NC) {
            int nst = st_idx + 2; if (nst >= NSTG) nst -= NSTG;
            load_stage(sb + (uint32_t)nst * STGB,
                       Ahi, Alo, Bhi, Blo, m0, n0, (kc + 2) * BKC, K, tid);
            cp_commit();
        }

        const uint32_t st = sb + (uint32_t)st_idx * STGB;
#pragma unroll
        for (int ks = 0; ks < 2; ks++) {
            const uint32_t aB = st + aoff[ks];
            const uint32_t bB = st + 2u * OPB + boff[ks];

            uint32_t bh[2][4], bl[2][4];
#pragma unroll
            for (int pr = 0; pr < 2; pr++) {
                ldsm4(bh[pr], bB + (uint32_t)(pr * 1024));
                ldsm4(bl[pr], bB + OPB + (uint32_t)(pr * 1024));
            }
#pragma unroll
            for (int mt = 0; mt < 4; mt++) {
                uint32_t ah[4], al[4];
                ldsm4(ah, aB + (uint32_t)(mt * 1024));
                ldsm4(al, aB + OPB + (uint32_t)(mt * 1024));
#pragma unroll
                for (int nt = 0; nt < 4; nt++)
                    mma_bf16(acc[mt][nt], ah, &bh[nt >> 1][(nt & 1) * 2]);
#pragma unroll
                for (int nt = 0; nt < 4; nt++)
                    mma_bf16(acc[mt][nt], ah, &bl[nt >> 1][(nt & 1) * 2]);
#pragma unroll
                for (int nt = 0; nt < 4; nt++)
                    mma_bf16(acc[mt][nt], al, &bh[nt >> 1][(nt & 1) * 2]);
            }
        }
        if (++st_idx == NSTG) st_idx = 0;
    }

#pragma unroll
    for (int mt = 0; mt < 4; mt++) {
        const int row = m0 + wm * 64 + mt * 16 + g;
#pragma unroll
        for (int nt = 0; nt < 4; nt++) {
            const int col = n0 + wn * 32 + nt * 8 + tig * 2;
            if (Cf) {
                *(float2*)&Cf[(size_t)row * N + col] =
                    make_float2(acc[mt][nt][0], acc[mt][nt][1]);
                *(float2*)&Cf[(size_t)(row + 8) * N + col] =
                    make_float2(acc[mt][nt][2], acc[mt][nt][3]);
            } else {
                uint32_t h0 = packbf(acc[mt][nt][0], acc[mt][nt][1]);
                uint32_t h1 = packbf(acc[mt][nt][2], acc[mt][nt][3]);
                *(uint32_t*)&Chi[(size_t)row * N + col]       = h0;
                *(uint32_t*)&Chi[(size_t)(row + 8) * N + col] = h1;
                *(uint32_t*)&Clo[(size_t)row * N + col] =
                    lopackbf(h0, acc[mt][nt][0], acc[mt][nt][1]);
                *(uint32_t*)&Clo[(size_t)(row + 8) * N + col] =
                    lopackbf(h1, acc[mt][nt][2], acc[mt][nt][3]);
            }
        }
    }
}

// ---------------------------------------------------------------------------
// HMMA flash attention (causal), q-tile 128, 8 warps / 256 threads.
// Q hoisted into registers (staged through the K+V smem buffers: Q-hi spans
// the two K tiles, Q-lo the two V tiles — 128 rows x 272B = exactly 2 tiles).
// kv-tile 64; iterations per unit work halved vs q-tile 64. For the second
// diagonal tile (kt == 2qt+1) warps 0-3 (rows < 64, fully masked) skip all
// compute — math per output row identical to the q64 version.
// ---------------------------------------------------------------------------
#define SKVB   272
#define TILEB  (64 * SKVB)
#define ATTN_SMEM (4 * TILEB)              // 69632 B: K hi/lo + V hi/lo
#define CL2E   (0.08838834764831845f * 1.4426950408889634f)

__global__ __launch_bounds__(256)
void attn_mma(const __nv_bfloat16* __restrict__ qh,
              const __nv_bfloat16* __restrict__ ql,
              __nv_bfloat16* __restrict__ ohi,
              __nv_bfloat16* __restrict__ olo)
{
    extern __shared__ char sma[];
    const uint32_t sb = smem_u32(sma);
    const int qt = (int)gridDim.x - 1 - (int)blockIdx.x;   // heavy tiles first
    const int h = blockIdx.y, b = blockIdx.z;
    const int tid = threadIdx.x, lane = tid & 31, w = tid >> 5;   // w: 0..7
    const int g = lane >> 2, tig = lane & 3;
    const int lrow = lane & 15, lhalf = lane >> 4;
    const int brow = (lane & 7) | ((lane & 16) >> 1), bhalf = (lane >> 3) & 1;

    const uint32_t sKH = sb,             sKL = sb + TILEB;
    const uint32_t sVH = sb + 2 * TILEB, sVL = sb + 3 * TILEB;

    const size_t qrow0 = (size_t)b * TSEQ + (size_t)qt * 128;

    // ---- stage Q (128 rows) through K+V buffers, hoist to registers ----
    uint32_t qfh[8][4], qfl[8][4];
    {
        const __nv_bfloat16* qbh = qh + qrow0 * NQKV + h * HD;
        const __nv_bfloat16* qbl = ql + qrow0 * NQKV + h * HD;
#pragma unroll
        for (int it = 0; it < 8; it++) {
            int idx = tid + it * 256;           // 0..2047: 128 rows x 16 segs
            int r = idx >> 4, cs = idx & 15;
            uint32_t so = (uint32_t)(r * SKVB + cs * 16);
            size_t go = (size_t)r * NQKV + cs * 8;
            cpa16(sKH + so, qbh + go);          // Q-hi spans K-hi + K-lo tiles
            cpa16(sVH + so, qbl + go);          // Q-lo spans V-hi + V-lo tiles
        }
        cp_commit();
        cp_wait<0>();
        __syncthreads();
        const uint32_t qAh = sKH + (uint32_t)((w * 16 + lrow) * SKVB + lhalf * 16);
        const uint32_t qAl = sVH + (uint32_t)((w * 16 + lrow) * SKVB + lhalf * 16);
#pragma unroll
        for (int s = 0; s < 8; s++) {
            ldsm4(qfh[s], qAh + (uint32_t)(s * 32));
            ldsm4(qfl[s], qAl + (uint32_t)(s * 32));
        }
        __syncthreads();   // all Q reads done before K0/V0 overwrite
    }

    // ---- load K0, V0 (64 rows each) ----
    {
        const size_t kr0 = (size_t)b * TSEQ;
        const __nv_bfloat16* kh = qh + kr0 * NQKV + D_MODEL + h * HD;
        const __nv_bfloat16* kl = ql + kr0 * NQKV + D_MODEL + h * HD;
        const __nv_bfloat16* vh = qh + kr0 * NQKV + 2 * D_MODEL + h * HD;
        const __nv_bfloat16* vl = ql + kr0 * NQKV + 2 * D_MODEL + h * HD;
#pragma unroll
        for (int it = 0; it < 4; it++) {
            int idx = tid + it * 256;           // 0..1023: 64 rows x 16 segs
            int r = idx >> 4, cs = idx & 15;
            uint32_t so = (uint32_t)(r * SKVB + cs * 16);
            size_t go = (size_t)r * NQKV + cs * 8;
            cpa16(sKH + so, kh + go); cpa16(sKL + so, kl + go);
            cpa16(sVH + so, vh + go); cpa16(sVL + so, vl + go);
        }
    }
    cp_commit();
    cp_wait<0>();
    __syncthreads();

    float o[16][4];
#pragma unroll
    for (int t = 0; t < 16; t++)
#pragma unroll
        for (int q = 0; q < 4; q++) o[t][q] = 0.0f;
    float mi0 = -1e30f, mi1 = -1e30f, li0 = 0.0f, li1 = 0.0f;

    const uint32_t bH = sKH + (uint32_t)(brow * SKVB + bhalf * 16);
    const uint32_t bL = sKL + (uint32_t)(brow * SKVB + bhalf * 16);
    const uint32_t vH = sVH + (uint32_t)((lane & 15) * SKVB + (lane >> 4) * 16);
    const uint32_t vL = sVL + (uint32_t)((lane & 15) * SKVB + (lane >> 4) * 16);

    const int ktmax = 2 * qt + 1;
    for (int kt = 0; kt <= ktmax; kt++) {
        // warps 0-3 (rows < 64) are fully masked on the kt == 2qt+1 tile
        const bool active = (kt <= 2 * qt) || (w >= 4);
        float sc[8][4];

        if (active) {
            // ---- S = Q K^T (bf16x3), Q from registers ----
#pragma unroll
            for (int nt = 0; nt < 8; nt++)
#pragma unroll
                for (int q = 0; q < 4; q++) sc[nt][q] = 0.0f;

#pragma unroll
            for (int s = 0; s < 8; s++) {
                const uint32_t kb = (uint32_t)(s * 32);
                uint32_t kh4[4][4], kl4[4][4];
#pragma unroll
                for (int p = 0; p < 4; p++) {
                    ldsm4(kh4[p], bH + (uint32_t)(p * 16 * SKVB) + kb);
                    ldsm4(kl4[p], bL + (uint32_t)(p * 16 * SKVB) + kb);
                }
#pragma unroll
                for (int nt = 0; nt < 8; nt++)
                    mma_bf16(sc[nt], qfh[s], &kh4[nt >> 1][(nt & 1) * 2]);
#pragma unroll
                for (int nt = 0; nt < 8; nt++)
                    mma_bf16(sc[nt], qfh[s], &kl4[nt >> 1][(nt & 1) * 2]);
#pragma unroll
                for (int nt = 0; nt < 8; nt++)
                    mma_bf16(sc[nt], qfl[s], &kh4[nt >> 1][(nt & 1) * 2]);
            }

            // ---- causal mask on diagonal tiles (kt >= 2qt) ----
            if (kt >= 2 * qt) {
                const int moff = (kt - 2 * qt) * 64;
                const int r0 = w * 16 + g, r1 = r0 + 8;
#pragma unroll
                for (int nt = 0; nt < 8; nt++) {
                    const int c0 = nt * 8 + 2 * tig + moff;
                    if (c0     > r0) sc[nt][0] = -1e30f;
                    if (c0 + 1 > r0) sc[nt][1] = -1e30f;
                    if (c0     > r1) sc[nt][2] = -1e30f;
                    if (c0 + 1 > r1) sc[nt][3] = -1e30f;
                }
            }

            // ---- online softmax ----
            float m0 = -1e30f, m1 = -1e30f;
#pragma unroll
            for (int nt = 0; nt < 8; nt++) {
                m0 = fmaxf(m0, fmaxf(sc[nt][0], sc[nt][1]));
                m1 = fmaxf(m1, fmaxf(sc[nt][2], sc[nt][3]));
            }
            m0 = fmaxf(m0, __shfl_xor_sync(0xffffffffu, m0, 1));
            m0 = fmaxf(m0, __shfl_xor_sync(0xffffffffu, m0, 2));
            m1 = fmaxf(m1, __shfl_xor_sync(0xffffffffu, m1, 1));
            m1 = fmaxf(m1, __shfl_xor_sync(0xffffffffu, m1, 2));
            const float n0 = fmaxf(mi0, m0), n1 = fmaxf(mi1, m1);
            const float c0 = ex2f((mi0 - n0) * CL2E);
            const float c1 = ex2f((mi1 - n1) * CL2E);
            mi0 = n0; mi1 = n1;
            float r0 = 0.0f, r1 = 0.0f;
#pragma unroll
            for (int nt = 0; nt < 8; nt++) {
                sc[nt][0] = ex2f((sc[nt][0] - n0) * CL2E);
                sc[nt][1] = ex2f((sc[nt][1] - n0) * CL2E);
                sc[nt][2] = ex2f((sc[nt][2] - n1) * CL2E);
                sc[nt][3] = ex2f((sc[nt][3] - n1) * CL2E);
                r0 += sc[nt][0] + sc[nt][1];
                r1 += sc[nt][2] + sc[nt][3];
            }
            r0 += __shfl_xor_sync(0xffffffffu, r0, 1);
            r0 += __shfl_xor_sync(0xffffffffu, r0, 2);
            r1 += __shfl_xor_sync(0xffffffffu, r1, 1);
            r1 += __shfl_xor_sync(0xffffffffu, r1, 2);
            li0 = li0 * c0 + r0;
            li1 = li1 * c1 + r1;
#pragma unroll
            for (int t = 0; t < 16; t++) {
                o[t][0] *= c0; o[t][1] *= c0;
                o[t][2] *= c1; o[t][3] *= c1;
            }
        }

        // ---- prefetch K(kt+1): overlaps P·V below ----
        if (kt < ktmax) {
            __syncthreads();
            const size_t kr0 = (size_t)b * TSEQ + (size_t)(kt + 1) * 64;
            const __nv_bfloat16* kh = qh + kr0 * NQKV + D_MODEL + h * HD;
            const __nv_bfloat16* kl = ql + kr0 * NQKV + D_MODEL + h * HD;
#pragma unroll
            for (int it = 0; it < 4; it++) {
                int idx = tid + it * 256;
                int r = idx >> 4, cs = idx & 15;
                uint32_t so = (uint32_t)(r * SKVB + cs * 16);
                size_t go = (size_t)r * NQKV + cs * 8;
                cpa16(sKH + so, kh + go); cpa16(sKL + so, kl + go);
            }
            cp_commit();
            cp_wait<1>();
            __syncthreads();
        }

        // ---- O += P V (bf16x3) ----
        if (active) {
#pragma unroll
            for (int s = 0; s < 4; s++) {
                uint32_t phi[4], plo[4];
                phi[0] = packbf(sc[2*s][0],   sc[2*s][1]);
                phi[1] = packbf(sc[2*s][2],   sc[2*s][3]);
                phi[2] = packbf(sc[2*s+1][0], sc[2*s+1][1]);
                phi[3] = packbf(sc[2*s+1][2], sc[2*s+1][3]);
                plo[0] = lopackbf(phi[0], sc[2*s][0],   sc[2*s][1]);
                plo[1] = lopackbf(phi[1], sc[2*s][2],   sc[2*s][3]);
                plo[2] = lopackbf(phi[2], sc[2*s+1][0], sc[2*s+1][1]);
                plo[3] = lopackbf(phi[3], sc[2*s+1][2], sc[2*s+1][3]);

                const uint32_t vrow = (uint32_t)(s * 16 * SKVB);
#pragma unroll
                for (int p = 0; p < 8; p++) {
                    uint32_t vh4[4], vl4[4];
                    ldsm4t(vh4, vH + vrow + (uint32_t)(p * 32));
                    ldsm4t(vl4, vL + vrow + (uint32_t)(p * 32));
                    mma_bf16(o[2*p],   phi, &vh4[0]);
                    mma_bf16(o[2*p+1], phi, &vh4[2]);
                    mma_bf16(o[2*p],   plo, &vh4[0]);
                    mma_bf16(o[2*p+1], plo, &vh4[2]);
                    mma_bf16(o[2*p],   phi, &vl4[0]);
                    mma_bf16(o[2*p+1], phi, &vl4[2]);
                }
            }
        }

        // ---- prefetch V(kt+1): overlaps next S-phase ----
        if (kt < ktmax) {
            __syncthreads();
            const size_t kr0 = (size_t)b * TSEQ + (size_t)(kt + 1) * 64;
            const __nv_bfloat16* vh = qh + kr0 * NQKV + 2 * D_MODEL + h * HD;
            const __nv_bfloat16* vl = ql + kr0 * NQKV + 2 * D_MODEL + h * HD;
#pragma unroll
            for (int it = 0; it < 4; it++) {
                int idx = tid + it * 256;
                int r = idx >> 4, cs = idx & 15;
                uint32_t so = (uint32_t)(r * SKVB + cs * 16);
                size_t go = (size_t)r * NQKV + cs * 8;
                cpa16(sVH + so, vh + go); cpa16(sVL + so, vl + go);
            }
            cp_commit();
            cp_wait<1>();
            __syncthreads();
        }
    }

    // ---- epilogue: normalize, split bf16 hi/lo ----
    const float inv0 = 1.0f / li0, inv1 = 1.0f / li1;
    const size_t row0 = qrow0 + w * 16 + g, row1 = row0 + 8;
#pragma unroll
    for (int nt = 0; nt < 16; nt++) {
        const int col = h * HD + nt * 8 + 2 * tig;
        float a0 = o[nt][0] * inv0, a1 = o[nt][1] * inv0;
        float a2 = o[nt][2] * inv1, a3 = o[nt][3] * inv1;
        uint32_t h0 = packbf(a0, a1), h1 = packbf(a2, a3);
        *(uint32_t*)&ohi[row0 * D_MODEL + col] = h0;
        *(uint32_t*)&ohi[row1 * D_MODEL + col] = h1;
        *(uint32_t*)&olo[row0 * D_MODEL + col] = lopackbf(h0, a0, a1);
        *(uint32_t*)&olo[row1 * D_MODEL + col] = lopackbf(h1, a2, a3);
    }
}

// ---------------------------------------------------------------------------
extern "C" void kernel_launch(void* const* d_in, const int* in_sizes, int n_in,
                              void* d_out, int out_size)
{
    (void)in_sizes; (void)n_in; (void)out_size;
    const float* x      = (const float*)d_in[0];
    const float* w_qkv  = (const float*)d_in[1];
    const float* w_proj = (const float*)d_in[2];
    float* out = (float*)d_out;

    __nv_bfloat16 *qhi, *qlo, *xhi, *xlo, *ahi, *alo, *wqhi, *wqlo, *wphi, *wplo;
    cudaGetSymbolAddress((void**)&qhi,  g_qkvhi);
    cudaGetSymbolAddress((void**)&qlo,  g_qkvlo);
    cudaGetSymbolAddress((void**)&xhi,  g_xhi);
    cudaGetSymbolAddress((void**)&xlo,  g_xlo);
    cudaGetSymbolAddress((void**)&ahi,  g_ahi);
    cudaGetSymbolAddress((void**)&alo,  g_alo);
    cudaGetSymbolAddress((void**)&wqhi, g_wqhi);
    cudaGetSymbolAddress((void**)&wqlo, g_wqlo);
    cudaGetSymbolAddress((void**)&wphi, g_wphi);
    cudaGetSymbolAddress((void**)&wplo, g_wplo);

    cudaFuncSetAttribute(gemm_hmma,
                         cudaFuncAttributeMaxDynamicSharedMemorySize, GEMM_SMEM);
    cudaFuncSetAttribute(attn_mma,
                         cudaFuncAttributeMaxDynamicSharedMemorySize, ATTN_SMEM);

    const int nx = MTOT * D_MODEL;

    split_kernel<<<nx / 4 / 256, 256>>>(x, xhi, xlo, nx);
    tsplit_kernel<<<dim3(NQKV / 32, D_MODEL / 32), 256>>>(w_qkv, wqhi, wqlo,
                                                          D_MODEL, NQKV);
    tsplit_kernel<<<dim3(D_MODEL / 32, D_MODEL / 32), 256>>>(w_proj, wphi, wplo,
                                                             D_MODEL, D_MODEL);
    gemm_hmma<<<dim3(NQKV / 128, MTOT / 128), 256, GEMM_SMEM>>>(
        xhi, xlo, wqhi, wqlo, nullptr, qhi, qlo, MTOT, NQKV, D_MODEL);
    attn_mma<<<dim3(TSEQ / 128, NHEAD, BATCH), 256, ATTN_SMEM>>>(
        qhi, qlo, ahi, alo);
    gemm_hmma<<<dim3(D_MODEL / 128, MTOT / 128), 256, GEMM_SMEM>>>(
        ahi, alo, wphi, wplo, out, nullptr, nullptr, MTOT, D_MODEL, D_MODEL);
}

// round 15
// speedup vs baseline: 1.0173x; 1.0173x over previous
#include <cuda_runtime.h>
#include <cuda_bf16.h>
#include <cstdint>

#define D_MODEL 2048
#define NHEAD   16
#define HD      128
#define TSEQ    1024
#define BATCH   4
#define MTOT    (BATCH * TSEQ)     // 4096
#define NQKV    (3 * D_MODEL)      // 6144

// ---------------------------------------------------------------------------
// Scratch (__device__ globals — allocation-guard safe), 16B-aligned
// ---------------------------------------------------------------------------
__device__ __align__(16) __nv_bfloat16 g_qkvhi[MTOT * NQKV];
__device__ __align__(16) __nv_bfloat16 g_qkvlo[MTOT * NQKV];
__device__ __align__(16) __nv_bfloat16 g_xhi[MTOT * D_MODEL];
__device__ __align__(16) __nv_bfloat16 g_xlo[MTOT * D_MODEL];
__device__ __align__(16) __nv_bfloat16 g_ahi[MTOT * D_MODEL];
__device__ __align__(16) __nv_bfloat16 g_alo[MTOT * D_MODEL];
__device__ __align__(16) __nv_bfloat16 g_wqhi[NQKV * D_MODEL];
__device__ __align__(16) __nv_bfloat16 g_wqlo[NQKV * D_MODEL];
__device__ __align__(16) __nv_bfloat16 g_wphi[D_MODEL * D_MODEL];
__device__ __align__(16) __nv_bfloat16 g_wplo[D_MODEL * D_MODEL];

// ---------------------------------------------------------------------------
// helpers
// ---------------------------------------------------------------------------
__device__ __forceinline__ uint32_t smem_u32(const void* p) {
    uint32_t a;
    asm("{ .reg .u64 t; cvta.to.shared.u64 t, %1; cvt.u32.u64 %0, t; }"
        : "=r"(a) : "l"(p));
    return a;
}
__device__ __forceinline__ void cpa16(uint32_t dst, const void* src) {
    asm volatile("cp.async.cg.shared.global [%0], [%1], 16;" :: "r"(dst), "l"(src));
}
__device__ __forceinline__ void cp_commit() { asm volatile("cp.async.commit_group;"); }
template <int N> __device__ __forceinline__ void cp_wait() {
    asm volatile("cp.async.wait_group %0;" :: "n"(N));
}
__device__ __forceinline__ void ldsm4(uint32_t* r, uint32_t a) {
    asm volatile("ldmatrix.sync.aligned.m8n8.x4.shared.b16 {%0,%1,%2,%3}, [%4];"
        : "=r"(r[0]), "=r"(r[1]), "=r"(r[2]), "=r"(r[3]) : "r"(a));
}
__device__ __forceinline__ void ldsm4t(uint32_t* r, uint32_t a) {
    asm volatile("ldmatrix.sync.aligned.m8n8.x4.trans.shared.b16 {%0,%1,%2,%3}, [%4];"
        : "=r"(r[0]), "=r"(r[1]), "=r"(r[2]), "=r"(r[3]) : "r"(a));
}
__device__ __forceinline__ void mma_bf16(float* c, const uint32_t* a,
                                         const uint32_t* b) {
    asm volatile(
        "mma.sync.aligned.m16n8k16.row.col.f32.bf16.bf16.f32 "
        "{%0,%1,%2,%3}, {%4,%5,%6,%7}, {%8,%9}, {%0,%1,%2,%3};"
        : "+f"(c[0]), "+f"(c[1]), "+f"(c[2]), "+f"(c[3])
        : "r"(a[0]), "r"(a[1]), "r"(a[2]), "r"(a[3]), "r"(b[0]), "r"(b[1]));
}
__device__ __forceinline__ uint32_t packbf(float e0, float e1) {
    uint32_t r;
    asm("cvt.rn.bf16x2.f32 %0, %1, %2;" : "=r"(r) : "f"(e1), "f"(e0));
    return r;
}
__device__ __forceinline__ uint32_t lopackbf(uint32_t hipack, float e0, float e1) {
    float h0 = __uint_as_float(hipack << 16);
    float h1 = __uint_as_float(hipack & 0xffff0000u);
    return packbf(e0 - h0, e1 - h1);
}
__device__ __forceinline__ float ex2f(float x) {
    float y;
    asm("ex2.approx.ftz.f32 %0, %1;" : "=f"(y) : "f"(x));
    return y;
}
// 64B-row swizzle: bits [4:5] ^= bits [7:8]; apply to full sub-bit-10 offset.
__device__ __forceinline__ uint32_t swz(uint32_t off) {
    return off ^ (((off >> 7) & 3u) << 4);
}

// ---------------------------------------------------------------------------
// Split fp32 -> (hi, lo) bf16 (elementwise)
// ---------------------------------------------------------------------------
__global__ __launch_bounds__(256)
void split_kernel(const float* __restrict__ in, __nv_bfloat16* __restrict__ hi,
                  __nv_bfloat16* __restrict__ lo, int n)
{
    int i = (blockIdx.x * 256 + threadIdx.x) * 4;
    if (i >= n) return;
    float4 v = *(const float4*)(in + i);
    uint32_t h0 = packbf(v.x, v.y);
    uint32_t h1 = packbf(v.z, v.w);
    *(uint32_t*)(hi + i)     = h0;
    *(uint32_t*)(hi + i + 2) = h1;
    *(uint32_t*)(lo + i)     = lopackbf(h0, v.x, v.y);
    *(uint32_t*)(lo + i + 2) = lopackbf(h1, v.z, v.w);
}

// ---------------------------------------------------------------------------
// Transpose + split: W fp32 [K][N] -> Whi/Wlo bf16 [N][K]
// ---------------------------------------------------------------------------
__global__ __launch_bounds__(256)
void tsplit_kernel(const float* __restrict__ W, __nv_bfloat16* __restrict__ hi,
                   __nv_bfloat16* __restrict__ lo, int K, int N)
{
    __shared__ float t[32][33];
    const int n0 = blockIdx.x * 32, k0 = blockIdx.y * 32;
    const int x = threadIdx.x & 31, y = threadIdx.x >> 5;
#pragma unroll
    for (int i = 0; i < 4; i++)
        t[y + 8 * i][x] = W[(size_t)(k0 + y + 8 * i) * N + n0 + x];
    __syncthreads();
#pragma unroll
    for (int i = 0; i < 4; i++) {
        float v = t[x][y + 8 * i];
        __nv_bfloat16 h = __float2bfloat16(v);
        size_t o = (size_t)(n0 + y + 8 * i) * K + k0 + x;
        hi[o] = h;
        lo[o] = __float2bfloat16(v - __bfloat162float(h));
    }
}

// ---------------------------------------------------------------------------
// HMMA bf16x3 GEMM — byte-identical to round 9/11/13 (proven 72% tensor)
// ---------------------------------------------------------------------------
#define BKC        32
#define OPB        (128 * 64)
#define STGB       (4 * OPB)
#define NSTG       3
#define GEMM_SMEM  (NSTG * STGB)

__device__ __forceinline__ void load_op(uint32_t dstb,
                                        const __nv_bfloat16* __restrict__ src,
                                        int r0, int k0, int K, int tid)
{
#pragma unroll
    for (int t = 0; t < 2; t++) {
        const int i = tid + t * 256;
        const int row = i >> 2, seg = i & 3;
        cpa16(dstb + swz((uint32_t)(row * 64 + seg * 16)),
              src + (size_t)(r0 + row) * K + k0 + seg * 8);
    }
}

__device__ __forceinline__ void load_stage(
    uint32_t sbase,
    const __nv_bfloat16* __restrict__ Ahi, const __nv_bfloat16* __restrict__ Alo,
    const __nv_bfloat16* __restrict__ Bhi, const __nv_bfloat16* __restrict__ Blo,
    int m0, int n0, int k0, int K, int tid)
{
    load_op(sbase + 0 * OPB, Ahi, m0, k0, K, tid);
    load_op(sbase + 1 * OPB, Alo, m0, k0, K, tid);
    load_op(sbase + 2 * OPB, Bhi, n0, k0, K, tid);
    load_op(sbase + 3 * OPB, Blo, n0, k0, K, tid);
}

__global__ __launch_bounds__(256, 2)
void gemm_hmma(const __nv_bfloat16* __restrict__ Ahi,
               const __nv_bfloat16* __restrict__ Alo,
               const __nv_bfloat16* __restrict__ Bhi,
               const __nv_bfloat16* __restrict__ Blo,
               float* __restrict__ Cf,
               __nv_bfloat16* __restrict__ Chi,
               __nv_bfloat16* __restrict__ Clo,
               int M, int N, int K)
{
    extern __shared__ char smc[];
    const uint32_t sb = smem_u32(smc);
    const int tid  = threadIdx.x;
    const int wid  = tid >> 5, lane = tid & 31;
    const int wm   = wid >> 2;
    const int wn   = wid & 3;
    const int g    = lane >> 2;
    const int tig  = lane & 3;
    const int m0 = blockIdx.y * 128, n0 = blockIdx.x * 128;

    const int lrow  = lane & 15;
    const int lhalf = lane >> 4;
    const int brow  = (lane & 7) | ((lane & 16) >> 1);
    const int bhalf = (lane >> 3) & 1;

    uint32_t aoff[2], boff[2];
#pragma unroll
    for (int ks = 0; ks < 2; ks++) {
        aoff[ks] = swz((uint32_t)((wm * 64 + lrow) * 64 + lhalf * 16 + ks * 32));
        boff[ks] = swz((uint32_t)((wn * 32 + brow) * 64 + bhalf * 16 + ks * 32));
    }

    float acc[4][4][4];
#pragma unroll
    for (int mt = 0; mt < 4; mt++)
#pragma unroll
        for (int nt = 0; nt < 4; nt++)
#pragma unroll
            for (int q = 0; q < 4; q++) acc[mt][nt][q] = 0.0f;

    const int NC = K / BKC;

    load_stage(sb, Ahi, Alo, Bhi, Blo, m0, n0, 0, K, tid);
    cp_commit();
    load_stage(sb + STGB, Ahi, Alo, Bhi, Blo, m0, n0, BKC, K, tid);
    cp_commit();

    int st_idx = 0;
    for (int kc = 0; kc < NC; kc++) {
        if (kc + 1 < NC) cp_wait<1>(); else cp_wait<0>();
        __syncthreads();

        if (kc + 2 < NC) {
            int nst = st_idx + 2; if (nst >= NSTG) nst -= NSTG;
            load_stage(sb + (uint32_t)nst * STGB,
                       Ahi, Alo, Bhi, Blo, m0, n0, (kc + 2) * BKC, K, tid);
            cp_commit();
        }

        const uint32_t st = sb + (uint32_t)st_idx * STGB;
#pragma unroll
        for (int ks = 0; ks < 2; ks++) {
            const uint32_t aB = st + aoff[ks];
            const uint32_t bB = st + 2u * OPB + boff[ks];

            uint32_t bh[2][4], bl[2][4];
#pragma unroll
            for (int pr = 0; pr < 2; pr++) {
                ldsm4(bh[pr], bB + (uint32_t)(pr * 1024));
                ldsm4(bl[pr], bB + OPB + (uint32_t)(pr * 1024));
            }
#pragma unroll
            for (int mt = 0; mt < 4; mt++) {
                uint32_t ah[4], al[4];
                ldsm4(ah, aB + (uint32_t)(mt * 1024));
                ldsm4(al, aB + OPB + (uint32_t)(mt * 1024));
#pragma unroll
                for (int nt = 0; nt < 4; nt++)
                    mma_bf16(acc[mt][nt], ah, &bh[nt >> 1][(nt & 1) * 2]);
#pragma unroll
                for (int nt = 0; nt < 4; nt++)
                    mma_bf16(acc[mt][nt], ah, &bl[nt >> 1][(nt & 1) * 2]);
#pragma unroll
                for (int nt = 0; nt < 4; nt++)
                    mma_bf16(acc[mt][nt], al, &bh[nt >> 1][(nt & 1) * 2]);
            }
        }
        if (++st_idx == NSTG) st_idx = 0;
    }

#pragma unroll
    for (int mt = 0; mt < 4; mt++) {
        const int row = m0 + wm * 64 + mt * 16 + g;
#pragma unroll
        for (int nt = 0; nt < 4; nt++) {
            const int col = n0 + wn * 32 + nt * 8 + tig * 2;
            if (Cf) {
                *(float2*)&Cf[(size_t)row * N + col] =
                    make_float2(acc[mt][nt][0], acc[mt][nt][1]);
                *(float2*)&Cf[(size_t)(row + 8) * N + col] =
                    make_float2(acc[mt][nt][2], acc[mt][nt][3]);
            } else {
                uint32_t h0 = packbf(acc[mt][nt][0], acc[mt][nt][1]);
                uint32_t h1 = packbf(acc[mt][nt][2], acc[mt][nt][3]);
                *(uint32_t*)&Chi[(size_t)row * N + col]       = h0;
                *(uint32_t*)&Chi[(size_t)(row + 8) * N + col] = h1;
                *(uint32_t*)&Clo[(size_t)row * N + col] =
                    lopackbf(h0, acc[mt][nt][0], acc[mt][nt][1]);
                *(uint32_t*)&Clo[(size_t)(row + 8) * N + col] =
                    lopackbf(h1, acc[mt][nt][2], acc[mt][nt][3]);
            }
        }
    }
}

// ---------------------------------------------------------------------------
// HMMA flash attention (causal), q-tile 64, Q in registers (R13), with
// DOUBLE-BUFFERED V: K(kt+1)+V(kt+1) prefetched in ONE group right after
// softmax (barrier proves K(kt) reads done); V(kt+1) lands in the alternate
// V buffer so P·V still reads V(kt). One wait + one barrier per iteration.
// smem = 6 tiles (K hi/lo, V0 hi/lo, V1 hi/lo) = 104448 B -> 2 CTAs/SM.
// ---------------------------------------------------------------------------
#define SKVB   272
#define TILEB  (64 * SKVB)
#define ATTN_SMEM (6 * TILEB)              // 104448
#define CL2E   (0.08838834764831845f * 1.4426950408889634f)

__global__ __launch_bounds__(128)
void attn_mma(const __nv_bfloat16* __restrict__ qh,
              const __nv_bfloat16* __restrict__ ql,
              __nv_bfloat16* __restrict__ ohi,
              __nv_bfloat16* __restrict__ olo)
{
    extern __shared__ char sma[];
    const uint32_t sb = smem_u32(sma);
    const int qt = (int)gridDim.x - 1 - (int)blockIdx.x;
    const int h = blockIdx.y, b = blockIdx.z;
    const int tid = threadIdx.x, lane = tid & 31, w = tid >> 5;
    const int g = lane >> 2, tig = lane & 3;
    const int lrow = lane & 15, lhalf = lane >> 4;
    const int brow = (lane & 7) | ((lane & 16) >> 1), bhalf = (lane >> 3) & 1;

    const uint32_t sKH = sb,             sKL = sb + TILEB;
    const uint32_t sV0 = sb + 2 * TILEB;                 // V buffers: [V0H V0L][V1H V1L]

    const size_t qrow0 = (size_t)b * TSEQ + (size_t)qt * 64;

    // ---- stage Q through V0 buffers, hoist fragments to registers ----
    uint32_t qfh[8][4], qfl[8][4];
    {
        const __nv_bfloat16* qbh = qh + qrow0 * NQKV + h * HD;
        const __nv_bfloat16* qbl = ql + qrow0 * NQKV + h * HD;
#pragma unroll
        for (int it = 0; it < 8; it++) {
            int idx = tid + it * 128;
            int r = idx >> 4, cs = idx & 15;
            uint32_t so = (uint32_t)(r * SKVB + cs * 16);
            size_t go = (size_t)r * NQKV + cs * 8;
            cpa16(sV0 + so, qbh + go);
            cpa16(sV0 + TILEB + so, qbl + go);
        }
        cp_commit();
        cp_wait<0>();
        __syncthreads();
        const uint32_t qAh = sV0 + (uint32_t)((w * 16 + lrow) * SKVB + lhalf * 16);
        const uint32_t qAl = sV0 + TILEB + (uint32_t)((w * 16 + lrow) * SKVB + lhalf * 16);
#pragma unroll
        for (int s = 0; s < 8; s++) {
            ldsm4(qfh[s], qAh + (uint32_t)(s * 32));
            ldsm4(qfl[s], qAl + (uint32_t)(s * 32));
        }
        __syncthreads();   // all Q reads done before V0 is overwritten
    }

    // ---- load K0 and V0 (into V buffer 0) ----
    {
        const size_t kr0 = (size_t)b * TSEQ;
        const __nv_bfloat16* kh = qh + kr0 * NQKV + D_MODEL + h * HD;
        const __nv_bfloat16* kl = ql + kr0 * NQKV + D_MODEL + h * HD;
        const __nv_bfloat16* vh = qh + kr0 * NQKV + 2 * D_MODEL + h * HD;
        const __nv_bfloat16* vl = ql + kr0 * NQKV + 2 * D_MODEL + h * HD;
#pragma unroll
        for (int it = 0; it < 8; it++) {
            int idx = tid + it * 128;
            int r = idx >> 4, cs = idx & 15;
            uint32_t so = (uint32_t)(r * SKVB + cs * 16);
            size_t go = (size_t)r * NQKV + cs * 8;
            cpa16(sKH + so, kh + go);         cpa16(sKL + so, kl + go);
            cpa16(sV0 + so, vh + go);         cpa16(sV0 + TILEB + so, vl + go);
        }
    }
    cp_commit();
    cp_wait<0>();
    __syncthreads();

    float o[16][4];
#pragma unroll
    for (int t = 0; t < 16; t++)
#pragma unroll
        for (int q = 0; q < 4; q++) o[t][q] = 0.0f;
    float mi0 = -1e30f, mi1 = -1e30f, li0 = 0.0f, li1 = 0.0f;

    const uint32_t bH = sKH + (uint32_t)(brow * SKVB + bhalf * 16);
    const uint32_t bL = sKL + (uint32_t)(brow * SKVB + bhalf * 16);
    const uint32_t vOff = (uint32_t)((lane & 15) * SKVB + (lane >> 4) * 16);

    for (int kt = 0; kt <= qt; kt++) {
        // ---- S = Q K^T (bf16x3), Q from registers ----
        float sc[8][4];
#pragma unroll
        for (int nt = 0; nt < 8; nt++)
#pragma unroll
            for (int q = 0; q < 4; q++) sc[nt][q] = 0.0f;

#pragma unroll
        for (int s = 0; s < 8; s++) {
            const uint32_t kb = (uint32_t)(s * 32);
            uint32_t kh4[4][4], kl4[4][4];
#pragma unroll
            for (int p = 0; p < 4; p++) {
                ldsm4(kh4[p], bH + (uint32_t)(p * 16 * SKVB) + kb);
                ldsm4(kl4[p], bL + (uint32_t)(p * 16 * SKVB) + kb);
            }
#pragma unroll
            for (int nt = 0; nt < 8; nt++)
                mma_bf16(sc[nt], qfh[s], &kh4[nt >> 1][(nt & 1) * 2]);
#pragma unroll
            for (int nt = 0; nt < 8; nt++)
                mma_bf16(sc[nt], qfh[s], &kl4[nt >> 1][(nt & 1) * 2]);
#pragma unroll
            for (int nt = 0; nt < 8; nt++)
                mma_bf16(sc[nt], qfl[s], &kh4[nt >> 1][(nt & 1) * 2]);
        }

        // ---- causal mask (diagonal tile only) ----
        if (kt == qt) {
            const int r0 = w * 16 + g, r1 = r0 + 8;
#pragma unroll
            for (int nt = 0; nt < 8; nt++) {
                const int c0 = nt * 8 + 2 * tig;
                if (c0     > r0) sc[nt][0] = -1e30f;
                if (c0 + 1 > r0) sc[nt][1] = -1e30f;
                if (c0     > r1) sc[nt][2] = -1e30f;
                if (c0 + 1 > r1) sc[nt][3] = -1e30f;
            }
        }

        // ---- online softmax ----
        float m0 = -1e30f, m1 = -1e30f;
#pragma unroll
        for (int nt = 0; nt < 8; nt++) {
            m0 = fmaxf(m0, fmaxf(sc[nt][0], sc[nt][1]));
            m1 = fmaxf(m1, fmaxf(sc[nt][2], sc[nt][3]));
        }
        m0 = fmaxf(m0, __shfl_xor_sync(0xffffffffu, m0, 1));
        m0 = fmaxf(m0, __shfl_xor_sync(0xffffffffu, m0, 2));
        m1 = fmaxf(m1, __shfl_xor_sync(0xffffffffu, m1, 1));
        m1 = fmaxf(m1, __shfl_xor_sync(0xffffffffu, m1, 2));
        const float n0 = fmaxf(mi0, m0), n1 = fmaxf(mi1, m1);
        const float c0 = ex2f((mi0 - n0) * CL2E);
        const float c1 = ex2f((mi1 - n1) * CL2E);
        mi0 = n0; mi1 = n1;
        float r0 = 0.0f, r1 = 0.0f;
#pragma unroll
        for (int nt = 0; nt < 8; nt++) {
            sc[nt][0] = ex2f((sc[nt][0] - n0) * CL2E);
            sc[nt][1] = ex2f((sc[nt][1] - n0) * CL2E);
            sc[nt][2] = ex2f((sc[nt][2] - n1) * CL2E);
            sc[nt][3] = ex2f((sc[nt][3] - n1) * CL2E);
            r0 += sc[nt][0] + sc[nt][1];
            r1 += sc[nt][2] + sc[nt][3];
        }
        r0 += __shfl_xor_sync(0xffffffffu, r0, 1);
        r0 += __shfl_xor_sync(0xffffffffu, r0, 2);
        r1 += __shfl_xor_sync(0xffffffffu, r1, 1);
        r1 += __shfl_xor_sync(0xffffffffu, r1, 2);
        li0 = li0 * c0 + r0;
        li1 = li1 * c1 + r1;
#pragma unroll
        for (int t = 0; t < 16; t++) {
            o[t][0] *= c0; o[t][1] *= c0;
            o[t][2] *= c1; o[t][3] *= c1;
        }

        // ---- prefetch K(kt+1) + V(kt+1) (ONE group); V into alt buffer ----
        if (kt < qt) {
            __syncthreads();   // all warps finished reading K(kt)
            const size_t kr0 = (size_t)b * TSEQ + (size_t)(kt + 1) * 64;
            const __nv_bfloat16* kh = qh + kr0 * NQKV + D_MODEL + h * HD;
            const __nv_bfloat16* kl = ql + kr0 * NQKV + D_MODEL + h * HD;
            const __nv_bfloat16* vh = qh + kr0 * NQKV + 2 * D_MODEL + h * HD;
            const __nv_bfloat16* vl = ql + kr0 * NQKV + 2 * D_MODEL + h * HD;
            const uint32_t vDst = sV0 + (uint32_t)(((kt + 1) & 1) * 2) * TILEB;
#pragma unroll
            for (int it = 0; it < 8; it++) {
                int idx = tid + it * 128;
                int r = idx >> 4, cs = idx & 15;
                uint32_t so = (uint32_t)(r * SKVB + cs * 16);
                size_t go = (size_t)r * NQKV + cs * 8;
                cpa16(sKH + so, kh + go);          cpa16(sKL + so, kl + go);
                cpa16(vDst + so, vh + go);         cpa16(vDst + TILEB + so, vl + go);
            }
            cp_commit();
        }

        // ---- O += P V (bf16x3) from V buffer (kt & 1) ----
        const uint32_t vCur = sV0 + (uint32_t)((kt & 1) * 2) * TILEB;
        const uint32_t vH = vCur + vOff, vL = vCur + TILEB + vOff;
#pragma unroll
        for (int s = 0; s < 4; s++) {
            uint32_t phi[4], plo[4];
            phi[0] = packbf(sc[2*s][0],   sc[2*s][1]);
            phi[1] = packbf(sc[2*s][2],   sc[2*s][3]);
            phi[2] = packbf(sc[2*s+1][0], sc[2*s+1][1]);
            phi[3] = packbf(sc[2*s+1][2], sc[2*s+1][3]);
            plo[0] = lopackbf(phi[0], sc[2*s][0],   sc[2*s][1]);
            plo[1] = lopackbf(phi[1], sc[2*s][2],   sc[2*s][3]);
            plo[2] = lopackbf(phi[2], sc[2*s+1][0], sc[2*s+1][1]);
            plo[3] = lopackbf(phi[3], sc[2*s+1][2], sc[2*s+1][3]);

            const uint32_t vrow = (uint32_t)(s * 16 * SKVB);
#pragma unroll
            for (int p = 0; p < 8; p++) {
                uint32_t vh4[4], vl4[4];
                ldsm4t(vh4, vH + vrow + (uint32_t)(p * 32));
                ldsm4t(vl4, vL + vrow + (uint32_t)(p * 32));
                mma_bf16(o[2*p],   phi, &vh4[0]);
                mma_bf16(o[2*p+1], phi, &vh4[2]);
                mma_bf16(o[2*p],   plo, &vh4[0]);
                mma_bf16(o[2*p+1], plo, &vh4[2]);
                mma_bf16(o[2*p],   phi, &vl4[0]);
                mma_bf16(o[2*p+1], phi, &vl4[2]);
            }
        }

        // ---- drain the K+V prefetch; one barrier per iteration ----
        if (kt < qt) {
            cp_wait<0>();
            __syncthreads();
        }
    }

    // ---- epilogue: normalize, split bf16 hi/lo ----
    const float inv0 = 1.0f / li0, inv1 = 1.0f / li1;
    const size_t row0 = qrow0 + w * 16 + g, row1 = row0 + 8;
#pragma unroll
    for (int nt = 0; nt < 16; nt++) {
        const int col = h * HD + nt * 8 + 2 * tig;
        float a0 = o[nt][0] * inv0, a1 = o[nt][1] * inv0;
        float a2 = o[nt][2] * inv1, a3 = o[nt][3] * inv1;
        uint32_t h0 = packbf(a0, a1), h1 = packbf(a2, a3);
        *(uint32_t*)&ohi[row0 * D_MODEL + col] = h0;
        *(uint32_t*)&ohi[row1 * D_MODEL + col] = h1;
        *(uint32_t*)&olo[row0 * D_MODEL + col] = lopackbf(h0, a0, a1);
        *(uint32_t*)&olo[row1 * D_MODEL + col] = lopackbf(h1, a2, a3);
    }
}

// ---------------------------------------------------------------------------
extern "C" void kernel_launch(void* const* d_in, const int* in_sizes, int n_in,
                              void* d_out, int out_size)
{
    (void)in_sizes; (void)n_in; (void)out_size;
    const float* x      = (const float*)d_in[0];
    const float* w_qkv  = (const float*)d_in[1];
    const float* w_proj = (const float*)d_in[2];
    float* out = (float*)d_out;

    __nv_bfloat16 *qhi, *qlo, *xhi, *xlo, *ahi, *alo, *wqhi, *wqlo, *wphi, *wplo;
    cudaGetSymbolAddress((void**)&qhi,  g_qkvhi);
    cudaGetSymbolAddress((void**)&qlo,  g_qkvlo);
    cudaGetSymbolAddress((void**)&xhi,  g_xhi);
    cudaGetSymbolAddress((void**)&xlo,  g_xlo);
    cudaGetSymbolAddress((void**)&ahi,  g_ahi);
    cudaGetSymbolAddress((void**)&alo,  g_alo);
    cudaGetSymbolAddress((void**)&wqhi, g_wqhi);
    cudaGetSymbolAddress((void**)&wqlo, g_wqlo);
    cudaGetSymbolAddress((void**)&wphi, g_wphi);
    cudaGetSymbolAddress((void**)&wplo, g_wplo);

    cudaFuncSetAttribute(gemm_hmma,
                         cudaFuncAttributeMaxDynamicSharedMemorySize, GEMM_SMEM);
    cudaFuncSetAttribute(attn_mma,
                         cudaFuncAttributeMaxDynamicSharedMemorySize, ATTN_SMEM);

    const int nx = MTOT * D_MODEL;

    split_kernel<<<nx / 4 / 256, 256>>>(x, xhi, xlo, nx);
    tsplit_kernel<<<dim3(NQKV / 32, D_MODEL / 32), 256>>>(w_qkv, wqhi, wqlo,
                                                          D_MODEL, NQKV);
    tsplit_kernel<<<dim3(D_MODEL / 32, D_MODEL / 32), 256>>>(w_proj, wphi, wplo,
                                                             D_MODEL, D_MODEL);
    gemm_hmma<<<dim3(NQKV / 128, MTOT / 128), 256, GEMM_SMEM>>>(
        xhi, xlo, wqhi, wqlo, nullptr, qhi, qlo, MTOT, NQKV, D_MODEL);
    attn_mma<<<dim3(TSEQ / 64, NHEAD, BATCH), 128, ATTN_SMEM>>>(
        qhi, qlo, ahi, alo);
    gemm_hmma<<<dim3(D_MODEL / 128, MTOT / 128), 256, GEMM_SMEM>>>(
        ahi, alo, wphi, wplo, out, nullptr, nullptr, MTOT, D_MODEL, D_MODEL);
}